// round 1
// baseline (speedup 1.0000x reference)
#include <cuda_runtime.h>

// Problem constants
#define B_SZ   4
#define NSEQ   2048
#define EDIM   1024
#define INTD   1024
#define NHEAD  16
#define HDIM   64
#define MROWS  (B_SZ * NSEQ)      // 8192
#define SCALE  0.125f             // 1/sqrt(64)

// Scratch: projected Q/K/V and attention output (head-concat layout, row-major (B*N, INT))
__device__ float g_Qp[MROWS * INTD];
__device__ float g_Kp[MROWS * INTD];
__device__ float g_Vp[MROWS * INTD];
__device__ float g_Op[MROWS * INTD];

// ---------------------------------------------------------------------------
// GEMM + bias: C[M,N] = A[M,K] @ W[K,N] + bias[N]
// 64x64 block tile, BK=16, 256 threads (16x16), 4x4 microtile, float4 smem.
// ---------------------------------------------------------------------------
__global__ __launch_bounds__(256) void gemm_bias_kernel(
    const float* __restrict__ A, const float* __restrict__ W,
    const float* __restrict__ bias, float* __restrict__ C,
    int M, int N, int K)
{
    __shared__ float Ast[16][68];   // transposed A tile: [k][m]
    __shared__ float Bs[16][68];    // [k][n]

    const int tid = threadIdx.x;
    const int tx  = tid & 15;
    const int ty  = tid >> 4;
    const int bm  = blockIdx.y * 64;
    const int bn  = blockIdx.x * 64;

    float acc[4][4] = {};

    for (int k0 = 0; k0 < K; k0 += 16) {
        // Load A tile (64 rows x 16 k): one float4 per thread, transposed store.
        {
            int r = tid >> 2;          // 0..63
            int q = tid & 3;           // 0..3 (quad of 4 k values)
            float4 a = *(const float4*)&A[(size_t)(bm + r) * K + k0 + q * 4];
            Ast[q * 4 + 0][r] = a.x;
            Ast[q * 4 + 1][r] = a.y;
            Ast[q * 4 + 2][r] = a.z;
            Ast[q * 4 + 3][r] = a.w;
        }
        // Load B tile (16 k x 64 n): one float4 per thread.
        {
            int r = tid >> 4;          // 0..15
            int q = tid & 15;          // 0..15
            *(float4*)&Bs[r][q * 4] =
                *(const float4*)&W[(size_t)(k0 + r) * N + bn + q * 4];
        }
        __syncthreads();

        #pragma unroll
        for (int d = 0; d < 16; d++) {
            float4 ra = *(const float4*)&Ast[d][ty * 4];
            float4 rb = *(const float4*)&Bs[d][tx * 4];
            float a4[4] = {ra.x, ra.y, ra.z, ra.w};
            float b4[4] = {rb.x, rb.y, rb.z, rb.w};
            #pragma unroll
            for (int i = 0; i < 4; i++)
                #pragma unroll
                for (int j = 0; j < 4; j++)
                    acc[i][j] = fmaf(a4[i], b4[j], acc[i][j]);
        }
        __syncthreads();
    }

    float4 b4 = *(const float4*)&bias[bn + tx * 4];
    #pragma unroll
    for (int i = 0; i < 4; i++) {
        float4 o;
        o.x = acc[i][0] + b4.x;
        o.y = acc[i][1] + b4.y;
        o.z = acc[i][2] + b4.z;
        o.w = acc[i][3] + b4.w;
        *(float4*)&C[(size_t)(bm + ty * 4 + i) * N + bn + tx * 4] = o;
    }
}

// ---------------------------------------------------------------------------
// Flash-attention style: per block one (b,h) and a 64-row q-tile.
// Streams K/V in 64-row tiles, online softmax, P staged via smem.
// Layouts: Qp/Kp/Vp/Op row-major (B*N, INT); head h occupies cols [h*64, h*64+64).
// ---------------------------------------------------------------------------
#define AST 68   // padded smem row stride (floats)

__global__ __launch_bounds__(256) void attn_kernel(
    const float* __restrict__ Qp, const float* __restrict__ Kp,
    const float* __restrict__ Vp, float* __restrict__ Op)
{
    extern __shared__ float sm[];
    float* Qs = sm;                  // 64 x AST
    float* Ks = Qs + 64 * AST;       // 64 x AST
    float* Vs = Ks + 64 * AST;       // 64 x AST
    float* Ps = Vs + 64 * AST;       // 64 x AST

    const int tid = threadIdx.x;
    const int tx  = tid & 15;
    const int ty  = tid >> 4;
    const int bh  = blockIdx.y;            // 0..63
    const int b   = bh >> 4;
    const int h   = bh & 15;
    const int q0  = blockIdx.x * 64;

    const size_t base_q = (size_t)(b * NSEQ + q0) * INTD + h * HDIM;
    const size_t base_k = (size_t)(b * NSEQ) * INTD + h * HDIM;

    // Load Q tile (64x64 floats) once.
    #pragma unroll
    for (int it = 0; it < 4; it++) {
        int idx = tid + it * 256;
        int r = idx >> 4;
        int c = (idx & 15) * 4;
        *(float4*)&Qs[r * AST + c] = *(const float4*)&Qp[base_q + (size_t)r * INTD + c];
    }

    float acc[4][4] = {};
    float mrow[4], lrow[4];
    #pragma unroll
    for (int i = 0; i < 4; i++) { mrow[i] = -1e30f; lrow[i] = 0.f; }

    for (int kt = 0; kt < NSEQ / 64; kt++) {
        __syncthreads();   // protect Ks/Vs/Ps reuse (also orders Qs on first iter)
        #pragma unroll
        for (int it = 0; it < 4; it++) {
            int idx = tid + it * 256;
            int r = idx >> 4;
            int c = (idx & 15) * 4;
            size_t g = base_k + (size_t)(kt * 64 + r) * INTD + c;
            *(float4*)&Ks[r * AST + c] = *(const float4*)&Kp[g];
            *(float4*)&Vs[r * AST + c] = *(const float4*)&Vp[g];
        }
        __syncthreads();

        // S = (Q K^T) * scale, 4x4 per thread
        float s[4][4] = {};
        #pragma unroll
        for (int d = 0; d < 64; d += 4) {
            float4 qa[4], kb[4];
            #pragma unroll
            for (int i = 0; i < 4; i++) qa[i] = *(const float4*)&Qs[(ty * 4 + i) * AST + d];
            #pragma unroll
            for (int j = 0; j < 4; j++) kb[j] = *(const float4*)&Ks[(tx * 4 + j) * AST + d];
            #pragma unroll
            for (int i = 0; i < 4; i++)
                #pragma unroll
                for (int j = 0; j < 4; j++) {
                    s[i][j] = fmaf(qa[i].x, kb[j].x, s[i][j]);
                    s[i][j] = fmaf(qa[i].y, kb[j].y, s[i][j]);
                    s[i][j] = fmaf(qa[i].z, kb[j].z, s[i][j]);
                    s[i][j] = fmaf(qa[i].w, kb[j].w, s[i][j]);
                }
        }

        // Online softmax update (row stats shared across the 16 tx lanes via shfl).
        #pragma unroll
        for (int i = 0; i < 4; i++) {
            #pragma unroll
            for (int j = 0; j < 4; j++) s[i][j] *= SCALE;

            float tmax = fmaxf(fmaxf(s[i][0], s[i][1]), fmaxf(s[i][2], s[i][3]));
            #pragma unroll
            for (int off = 1; off < 16; off <<= 1)
                tmax = fmaxf(tmax, __shfl_xor_sync(0xffffffffu, tmax, off));
            float mnew = fmaxf(mrow[i], tmax);

            float p[4], rs = 0.f;
            #pragma unroll
            for (int j = 0; j < 4; j++) { p[j] = __expf(s[i][j] - mnew); rs += p[j]; }
            #pragma unroll
            for (int off = 1; off < 16; off <<= 1)
                rs += __shfl_xor_sync(0xffffffffu, rs, off);

            float corr = __expf(mrow[i] - mnew);
            lrow[i] = lrow[i] * corr + rs;
            mrow[i] = mnew;
            #pragma unroll
            for (int j = 0; j < 4; j++) acc[i][j] *= corr;

            *(float4*)&Ps[(ty * 4 + i) * AST + tx * 4] = make_float4(p[0], p[1], p[2], p[3]);
        }
        __syncthreads();   // Ps visible to all

        // O += P @ V   (64x64 @ 64x64)
        #pragma unroll 4
        for (int k = 0; k < 64; k++) {
            float4 v = *(const float4*)&Vs[k * AST + tx * 4];
            #pragma unroll
            for (int i = 0; i < 4; i++) {
                float pv = Ps[(ty * 4 + i) * AST + k];
                acc[i][0] = fmaf(pv, v.x, acc[i][0]);
                acc[i][1] = fmaf(pv, v.y, acc[i][1]);
                acc[i][2] = fmaf(pv, v.z, acc[i][2]);
                acc[i][3] = fmaf(pv, v.w, acc[i][3]);
            }
        }
    }

    // Normalize and store (head-concat layout => transpose+reshape is free).
    #pragma unroll
    for (int i = 0; i < 4; i++) {
        float inv = 1.f / lrow[i];
        float4 o;
        o.x = acc[i][0] * inv;
        o.y = acc[i][1] * inv;
        o.z = acc[i][2] * inv;
        o.w = acc[i][3] * inv;
        *(float4*)&Op[base_q + (size_t)(ty * 4 + i) * INTD + tx * 4] = o;
    }
}

// ---------------------------------------------------------------------------
// Launch
// ---------------------------------------------------------------------------
extern "C" void kernel_launch(void* const* d_in, const int* in_sizes, int n_in,
                              void* d_out, int out_size)
{
    const float* q  = (const float*)d_in[0];
    const float* k  = (const float*)d_in[1];
    const float* v  = (const float*)d_in[2];
    const float* wq = (const float*)d_in[3];
    const float* bq = (const float*)d_in[4];
    const float* wk = (const float*)d_in[5];
    const float* bk = (const float*)d_in[6];
    const float* wv = (const float*)d_in[7];
    const float* bv = (const float*)d_in[8];
    const float* wo = (const float*)d_in[9];
    const float* bo = (const float*)d_in[10];
    float* out = (float*)d_out;

    float *Qp, *Kp, *Vp, *Op;
    cudaGetSymbolAddress((void**)&Qp, g_Qp);
    cudaGetSymbolAddress((void**)&Kp, g_Kp);
    cudaGetSymbolAddress((void**)&Vp, g_Vp);
    cudaGetSymbolAddress((void**)&Op, g_Op);

    dim3 gblk(256);
    dim3 ggrid(INTD / 64, MROWS / 64);   // (16, 128)

    gemm_bias_kernel<<<ggrid, gblk>>>(q, wq, bq, Qp, MROWS, INTD, EDIM);
    gemm_bias_kernel<<<ggrid, gblk>>>(k, wk, bk, Kp, MROWS, INTD, EDIM);
    gemm_bias_kernel<<<ggrid, gblk>>>(v, wv, bv, Vp, MROWS, INTD, EDIM);

    int smem = 4 * 64 * AST * (int)sizeof(float);  // 69632 B
    cudaFuncSetAttribute(attn_kernel, cudaFuncAttributeMaxDynamicSharedMemorySize, smem);
    dim3 agrid(NSEQ / 64, B_SZ * NHEAD);           // (32, 64)
    attn_kernel<<<agrid, 256, smem>>>(Qp, Kp, Vp, Op);

    dim3 ogrid(EDIM / 64, MROWS / 64);
    gemm_bias_kernel<<<ogrid, gblk>>>(Op, wo, bo, out, MROWS, EDIM, INTD);
}

// round 3
// speedup vs baseline: 3.3097x; 3.3097x over previous
#include <cuda_runtime.h>
#include <cuda_bf16.h>
#include <cstdint>

// Problem constants
#define B_SZ   4
#define NSEQ   2048
#define EDIM   1024
#define INTD   1024
#define NHEAD  16
#define HDIM   64
#define MROWS  (B_SZ * NSEQ)          // 8192
#define KSC    0.1803368801111244f    // (1/sqrt(64)) * log2(e)

// ---------------------------------------------------------------------------
// Device scratch
// ---------------------------------------------------------------------------
// split inputs (activations)
__device__ __nv_bfloat16 g_qh[MROWS * EDIM], g_ql[MROWS * EDIM];
__device__ __nv_bfloat16 g_kh[MROWS * EDIM], g_kl[MROWS * EDIM];
__device__ __nv_bfloat16 g_vh[MROWS * EDIM], g_vl[MROWS * EDIM];
// split transposed weights [N][K]
__device__ __nv_bfloat16 g_wqh[INTD * EDIM], g_wql[INTD * EDIM];
__device__ __nv_bfloat16 g_wkh[INTD * EDIM], g_wkl[INTD * EDIM];
__device__ __nv_bfloat16 g_wvh[INTD * EDIM], g_wvl[INTD * EDIM];
__device__ __nv_bfloat16 g_woh[EDIM * INTD], g_wol[EDIM * INTD];
// projected Q/K/V (bf16 hi/lo, head-concat layout [token][INTD])
__device__ __nv_bfloat16 g_Qph[MROWS * INTD], g_Qpl[MROWS * INTD];
__device__ __nv_bfloat16 g_Kph[MROWS * INTD], g_Kpl[MROWS * INTD];
__device__ __nv_bfloat16 g_Vph[MROWS * INTD], g_Vpl[MROWS * INTD];
// attention output (bf16 hi/lo)
__device__ __nv_bfloat16 g_Oh[MROWS * INTD], g_Ol[MROWS * INTD];

// ---------------------------------------------------------------------------
// Helpers
// ---------------------------------------------------------------------------
__device__ __forceinline__ uint32_t smem_u32(const void* p) {
    uint32_t a;
    asm("{ .reg .u64 t; cvta.to.shared.u64 t, %1; cvt.u32.u64 %0, t; }"
        : "=r"(a) : "l"(p));
    return a;
}

__device__ __forceinline__ void sts128(uint32_t addr, uint4 v) {
    asm volatile("st.shared.v4.b32 [%0], {%1, %2, %3, %4};"
                 :: "r"(addr), "r"(v.x), "r"(v.y), "r"(v.z), "r"(v.w) : "memory");
}

__device__ __forceinline__ void ldsm4(uint32_t* r, uint32_t addr) {
    asm volatile("ldmatrix.sync.aligned.m8n8.x4.shared.b16 {%0,%1,%2,%3}, [%4];"
                 : "=r"(r[0]), "=r"(r[1]), "=r"(r[2]), "=r"(r[3]) : "r"(addr));
}

__device__ __forceinline__ void ldsm4t(uint32_t* r, uint32_t addr) {
    asm volatile("ldmatrix.sync.aligned.m8n8.x4.trans.shared.b16 {%0,%1,%2,%3}, [%4];"
                 : "=r"(r[0]), "=r"(r[1]), "=r"(r[2]), "=r"(r[3]) : "r"(addr));
}

// D += A(bf16) * B(bf16), m16n8k16, fp32 accum
__device__ __forceinline__ void mma_bf16(float* d, const uint32_t* a, const uint32_t* b) {
    asm volatile(
        "mma.sync.aligned.m16n8k16.row.col.f32.bf16.bf16.f32 "
        "{%0,%1,%2,%3}, {%4,%5,%6,%7}, {%8,%9}, {%0,%1,%2,%3};"
        : "+f"(d[0]), "+f"(d[1]), "+f"(d[2]), "+f"(d[3])
        : "r"(a[0]), "r"(a[1]), "r"(a[2]), "r"(a[3]), "r"(b[0]), "r"(b[1]));
}

// SW128-swizzled address inside a tile whose rows are 128 bytes (64 bf16)
__device__ __forceinline__ uint32_t swa(uint32_t base, int r, int k /*bf16 units, %8==0*/) {
    return base + (uint32_t)(r * 128 + ((((k >> 3) ^ (r & 7)) & 7) << 4));
}

__device__ __forceinline__ uint32_t pack_bf16(__nv_bfloat16 x, __nv_bfloat16 y) {
    __nv_bfloat162 t = __halves2bfloat162(x, y);
    return *(uint32_t*)&t;
}

__device__ __forceinline__ void split_pack(float x, float y, uint32_t& hi, uint32_t& lo) {
    __nv_bfloat16 hx = __float2bfloat16_rn(x);
    __nv_bfloat16 hy = __float2bfloat16_rn(y);
    hi = pack_bf16(hx, hy);
    lo = pack_bf16(__float2bfloat16_rn(x - __bfloat162float(hx)),
                   __float2bfloat16_rn(y - __bfloat162float(hy)));
}

// exp2 on the FMA pipe (no MUFU). y <= 0 expected; rel err ~1e-5.
__device__ __forceinline__ float exp2p(float y) {
    y = fmaxf(y, -80.0f);
    float fi = floorf(y);
    float f = y - fi;
    float p = 1.5403530e-4f;
    p = fmaf(p, f, 1.3333558e-3f);
    p = fmaf(p, f, 9.6181291e-3f);
    p = fmaf(p, f, 5.5504108e-2f);
    p = fmaf(p, f, 2.4022650e-1f);
    p = fmaf(p, f, 6.9314718e-1f);
    p = fmaf(p, f, 1.0f);
    int yi = (int)fi;
    return p * __int_as_float((yi + 127) << 23);
}

// ---------------------------------------------------------------------------
// Split fp32 -> bf16 hi/lo
// ---------------------------------------------------------------------------
__global__ __launch_bounds__(256) void split_kernel(
    const float* __restrict__ x, __nv_bfloat16* __restrict__ h,
    __nv_bfloat16* __restrict__ l, int n)
{
    int i = (blockIdx.x * 256 + threadIdx.x) * 4;
    if (i >= n) return;
    float4 v = *(const float4*)&x[i];
    uint32_t h0, l0, h1, l1;
    split_pack(v.x, v.y, h0, l0);
    split_pack(v.z, v.w, h1, l1);
    *(uint2*)&h[i] = make_uint2(h0, h1);
    *(uint2*)&l[i] = make_uint2(l0, l1);
}

// Transpose + split: W[K,N] fp32 -> [N,K] bf16 hi/lo
__global__ __launch_bounds__(256) void transpose_split_kernel(
    const float* __restrict__ W, __nv_bfloat16* __restrict__ Th,
    __nv_bfloat16* __restrict__ Tl, int K, int N)
{
    __shared__ float t[32][33];
    int n0 = blockIdx.x * 32, k0 = blockIdx.y * 32;
    int tx = threadIdx.x, ty = threadIdx.y;   // 32 x 8
    #pragma unroll
    for (int i = 0; i < 32; i += 8)
        t[ty + i][tx] = W[(size_t)(k0 + ty + i) * N + n0 + tx];
    __syncthreads();
    #pragma unroll
    for (int i = 0; i < 32; i += 8) {
        float v = t[tx][ty + i];
        __nv_bfloat16 hh = __float2bfloat16_rn(v);
        size_t o = (size_t)(n0 + ty + i) * K + k0 + tx;
        Th[o] = hh;
        Tl[o] = __float2bfloat16_rn(v - __bfloat162float(hh));
    }
}

// ---------------------------------------------------------------------------
// mma.sync split-bf16 GEMM:  C[M,N] = A[M,K] @ B[N,K]^T + bias
// BM=128, BN=128, BK=64; 8 warps (2m x 4n), warp tile 64x32.
// Output: fp32 (Cf) or bf16 hi/lo split (Ch/Cl).
// ---------------------------------------------------------------------------
__global__ __launch_bounds__(256) void gemm_mma(
    const __nv_bfloat16* __restrict__ Ah, const __nv_bfloat16* __restrict__ Al,
    const __nv_bfloat16* __restrict__ Bh, const __nv_bfloat16* __restrict__ Bl,
    const float* __restrict__ bias,
    float* __restrict__ Cf, __nv_bfloat16* __restrict__ Ch, __nv_bfloat16* __restrict__ Cl,
    int K, int N)
{
    extern __shared__ char smraw[];
    const uint32_t base = (smem_u32(smraw) + 1023u) & ~1023u;
    const uint32_t As_h = base, As_l = base + 16384;
    const uint32_t Bs_h = base + 32768, Bs_l = base + 49152;

    const int tid = threadIdx.x, lane = tid & 31, wid = tid >> 5;
    const int wm = wid >> 2, wn = wid & 3;
    const int bm = blockIdx.y * 128, bn = blockIdx.x * 128;
    const int lr = lane & 15, lco = (lane >> 4) * 8;

    float acc[4][4][4] = {};

    for (int k0 = 0; k0 < K; k0 += 64) {
        __syncthreads();
        #pragma unroll
        for (int t = 0; t < 16; t++) {
            const int which = t >> 2;
            const int id = tid + (t & 3) * 256;
            const int r = id >> 3, j = id & 7;
            const __nv_bfloat16* src = (which == 0) ? Ah : (which == 1) ? Al
                                     : (which == 2) ? Bh : Bl;
            const int row = ((which < 2) ? bm : bn) + r;
            uint4 v = *(const uint4*)&src[(size_t)row * K + k0 + j * 8];
            sts128(base + which * 16384 + r * 128 + ((j ^ (r & 7)) << 4), v);
        }
        __syncthreads();

        #pragma unroll
        for (int ks = 0; ks < 4; ks++) {
            const int kk = ks * 16 + lco;
            uint32_t ah[4][4], al_[4][4], bhf[4][2], blf[4][2];
            #pragma unroll
            for (int i = 0; i < 4; i++) {
                const int r = wm * 64 + i * 16 + lr;
                ldsm4(ah[i], swa(As_h, r, kk));
                ldsm4(al_[i], swa(As_l, r, kk));
            }
            #pragma unroll
            for (int bb = 0; bb < 2; bb++) {
                const int r = wn * 32 + bb * 16 + lr;
                uint32_t t4[4];
                ldsm4(t4, swa(Bs_h, r, kk));
                bhf[2*bb][0] = t4[0]; bhf[2*bb][1] = t4[2];
                bhf[2*bb+1][0] = t4[1]; bhf[2*bb+1][1] = t4[3];
                ldsm4(t4, swa(Bs_l, r, kk));
                blf[2*bb][0] = t4[0]; blf[2*bb][1] = t4[2];
                blf[2*bb+1][0] = t4[1]; blf[2*bb+1][1] = t4[3];
            }
            #pragma unroll
            for (int i = 0; i < 4; i++)
                #pragma unroll
                for (int j = 0; j < 4; j++) {
                    mma_bf16(acc[i][j], ah[i],  bhf[j]);
                    mma_bf16(acc[i][j], ah[i],  blf[j]);
                    mma_bf16(acc[i][j], al_[i], bhf[j]);
                }
        }
    }

    const int er = lane >> 2, ec = (lane & 3) * 2;
    #pragma unroll
    for (int i = 0; i < 4; i++) {
        const int r0 = bm + wm * 64 + i * 16 + er;
        #pragma unroll
        for (int j = 0; j < 4; j++) {
            const int col = bn + wn * 32 + j * 8 + ec;
            const float b0 = bias[col], b1 = bias[col + 1];
            const float v00 = acc[i][j][0] + b0, v01 = acc[i][j][1] + b1;
            const float v10 = acc[i][j][2] + b0, v11 = acc[i][j][3] + b1;
            if (Cf) {
                *(float2*)&Cf[(size_t)r0 * N + col]       = make_float2(v00, v01);
                *(float2*)&Cf[(size_t)(r0 + 8) * N + col] = make_float2(v10, v11);
            } else {
                uint32_t h, l;
                split_pack(v00, v01, h, l);
                *(uint32_t*)&Ch[(size_t)r0 * N + col] = h;
                *(uint32_t*)&Cl[(size_t)r0 * N + col] = l;
                split_pack(v10, v11, h, l);
                *(uint32_t*)&Ch[(size_t)(r0 + 8) * N + col] = h;
                *(uint32_t*)&Cl[(size_t)(r0 + 8) * N + col] = l;
            }
        }
    }
}

// ---------------------------------------------------------------------------
// Flash attention with mma.sync. CTA: one (b,h), 128 q-rows; 8 warps (16 q each).
// KV streamed in 64-key tiles; online softmax on FMA-pipe exp2; P regs -> A frags.
// ---------------------------------------------------------------------------
__global__ __launch_bounds__(256) void attn_mma(
    const __nv_bfloat16* __restrict__ Qh, const __nv_bfloat16* __restrict__ Ql,
    const __nv_bfloat16* __restrict__ Kh, const __nv_bfloat16* __restrict__ Kl,
    const __nv_bfloat16* __restrict__ Vh, const __nv_bfloat16* __restrict__ Vl,
    __nv_bfloat16* __restrict__ Oh, __nv_bfloat16* __restrict__ Ol)
{
    extern __shared__ char smraw[];
    const uint32_t base = (smem_u32(smraw) + 1023u) & ~1023u;
    const uint32_t Qs_h = base, Qs_l = base + 16384;
    const uint32_t Ks_h = base + 32768, Ks_l = base + 40960;
    const uint32_t Vs_h = base + 49152, Vs_l = base + 57344;

    const int tid = threadIdx.x, lane = tid & 31, wid = tid >> 5;
    const int b = blockIdx.y >> 4, h = blockIdx.y & 15;
    const int q0 = blockIdx.x * 128;
    const int lr = lane & 15, lco = (lane >> 4) * 8;

    // Stage Q (128 x 64) hi/lo into persistent smem
    #pragma unroll
    for (int t = 0; t < 4; t++) {
        const int id = tid + t * 256;          // 0..1023
        const int r = id >> 3, j = id & 7;
        const size_t g = (size_t)(b * NSEQ + q0 + r) * INTD + h * HDIM + j * 8;
        sts128(Qs_h + r * 128 + ((j ^ (r & 7)) << 4), *(const uint4*)&Qh[g]);
        sts128(Qs_l + r * 128 + ((j ^ (r & 7)) << 4), *(const uint4*)&Ql[g]);
    }

    float oacc[8][4] = {};
    float m0 = -1e30f, m1 = -1e30f, l0 = 0.f, l1 = 0.f;

    // prefetch kv tile 0
    uint4 pre[8];
    {
        const size_t tok0 = (size_t)(b * NSEQ);
        #pragma unroll
        for (int t = 0; t < 8; t++) {
            const int which = t >> 1;
            const int id = tid + (t & 1) * 256;
            const int r = id >> 3, j = id & 7;
            const __nv_bfloat16* src = (which == 0) ? Kh : (which == 1) ? Kl
                                     : (which == 2) ? Vh : Vl;
            pre[t] = *(const uint4*)&src[(tok0 + r) * INTD + h * HDIM + j * 8];
        }
    }
    __syncthreads();   // Q visible

    for (int kt = 0; kt < NSEQ / 64; kt++) {
        // store prefetched tile
        #pragma unroll
        for (int t = 0; t < 8; t++) {
            const int which = t >> 1;
            const int id = tid + (t & 1) * 256;
            const int r = id >> 3, j = id & 7;
            sts128(Ks_h + which * 8192 + r * 128 + ((j ^ (r & 7)) << 4), pre[t]);
        }
        __syncthreads();

        // prefetch next
        if (kt + 1 < NSEQ / 64) {
            const size_t tok0 = (size_t)(b * NSEQ + (kt + 1) * 64);
            #pragma unroll
            for (int t = 0; t < 8; t++) {
                const int which = t >> 1;
                const int id = tid + (t & 1) * 256;
                const int r = id >> 3, j = id & 7;
                const __nv_bfloat16* src = (which == 0) ? Kh : (which == 1) ? Kl
                                         : (which == 2) ? Vh : Vl;
                pre[t] = *(const uint4*)&src[(tok0 + r) * INTD + h * HDIM + j * 8];
            }
        }

        // ---- S = (Qh+Ql)(Kh+Kl)^T (3 combos), 16q x 64k per warp ----
        float sacc[8][4] = {};
        #pragma unroll
        for (int ks = 0; ks < 4; ks++) {
            const int kk = ks * 16 + lco;
            uint32_t qf_h[4], qf_l[4];
            ldsm4(qf_h, swa(Qs_h, wid * 16 + lr, kk));
            ldsm4(qf_l, swa(Qs_l, wid * 16 + lr, kk));
            uint32_t kb_h[8][2], kb_l[8][2];
            #pragma unroll
            for (int bb = 0; bb < 4; bb++) {
                uint32_t t4[4];
                ldsm4(t4, swa(Ks_h, bb * 16 + lr, kk));
                kb_h[2*bb][0] = t4[0]; kb_h[2*bb][1] = t4[2];
                kb_h[2*bb+1][0] = t4[1]; kb_h[2*bb+1][1] = t4[3];
                ldsm4(t4, swa(Ks_l, bb * 16 + lr, kk));
                kb_l[2*bb][0] = t4[0]; kb_l[2*bb][1] = t4[2];
                kb_l[2*bb+1][0] = t4[1]; kb_l[2*bb+1][1] = t4[3];
            }
            #pragma unroll
            for (int j = 0; j < 8; j++) {
                mma_bf16(sacc[j], qf_h, kb_h[j]);
                mma_bf16(sacc[j], qf_h, kb_l[j]);
                mma_bf16(sacc[j], qf_l, kb_h[j]);
            }
        }

        // ---- online softmax (2 rows per thread) ----
        float mx0 = -1e30f, mx1 = -1e30f;
        #pragma unroll
        for (int j = 0; j < 8; j++) {
            mx0 = fmaxf(mx0, fmaxf(sacc[j][0], sacc[j][1]));
            mx1 = fmaxf(mx1, fmaxf(sacc[j][2], sacc[j][3]));
        }
        mx0 = fmaxf(mx0, __shfl_xor_sync(0xffffffffu, mx0, 1));
        mx0 = fmaxf(mx0, __shfl_xor_sync(0xffffffffu, mx0, 2));
        mx1 = fmaxf(mx1, __shfl_xor_sync(0xffffffffu, mx1, 1));
        mx1 = fmaxf(mx1, __shfl_xor_sync(0xffffffffu, mx1, 2));
        const float mn0 = fmaxf(m0, mx0), mn1 = fmaxf(m1, mx1);
        const float c0 = exp2p((m0 - mn0) * KSC), c1 = exp2p((m1 - mn1) * KSC);
        m0 = mn0; m1 = mn1;

        float s0 = 0.f, s1 = 0.f;
        uint32_t pah0[8], pah1[8], pal0[8], pal1[8];
        #pragma unroll
        for (int j = 0; j < 8; j++) {
            const float p00 = exp2p((sacc[j][0] - mn0) * KSC);
            const float p01 = exp2p((sacc[j][1] - mn0) * KSC);
            const float p10 = exp2p((sacc[j][2] - mn1) * KSC);
            const float p11 = exp2p((sacc[j][3] - mn1) * KSC);
            s0 += p00 + p01; s1 += p10 + p11;
            split_pack(p00, p01, pah0[j], pal0[j]);
            split_pack(p10, p11, pah1[j], pal1[j]);
        }
        s0 += __shfl_xor_sync(0xffffffffu, s0, 1);
        s0 += __shfl_xor_sync(0xffffffffu, s0, 2);
        s1 += __shfl_xor_sync(0xffffffffu, s1, 1);
        s1 += __shfl_xor_sync(0xffffffffu, s1, 2);
        l0 = l0 * c0 + s0; l1 = l1 * c1 + s1;
        #pragma unroll
        for (int j = 0; j < 8; j++) {
            oacc[j][0] *= c0; oacc[j][1] *= c0;
            oacc[j][2] *= c1; oacc[j][3] *= c1;
        }

        // ---- O += P @ V (3 combos) ----
        #pragma unroll
        for (int t = 0; t < 4; t++) {
            const uint32_t a_h[4] = {pah0[2*t], pah1[2*t], pah0[2*t+1], pah1[2*t+1]};
            const uint32_t a_l[4] = {pal0[2*t], pal1[2*t], pal0[2*t+1], pal1[2*t+1]};
            uint32_t vb_h[8][2], vb_l[8][2];
            #pragma unroll
            for (int c = 0; c < 4; c++) {
                uint32_t t4[4];
                ldsm4t(t4, swa(Vs_h, t * 16 + lr, c * 16 + lco));
                vb_h[2*c][0] = t4[0]; vb_h[2*c][1] = t4[1];
                vb_h[2*c+1][0] = t4[2]; vb_h[2*c+1][1] = t4[3];
                ldsm4t(t4, swa(Vs_l, t * 16 + lr, c * 16 + lco));
                vb_l[2*c][0] = t4[0]; vb_l[2*c][1] = t4[1];
                vb_l[2*c+1][0] = t4[2]; vb_l[2*c+1][1] = t4[3];
            }
            #pragma unroll
            for (int j = 0; j < 8; j++) {
                mma_bf16(oacc[j], a_h, vb_h[j]);
                mma_bf16(oacc[j], a_h, vb_l[j]);
                mma_bf16(oacc[j], a_l, vb_h[j]);
            }
        }
        __syncthreads();   // done reading K/V before next store
    }

    // epilogue: O normalized, split to bf16 hi/lo (head-concat layout)
    const float inv0 = 1.0f / l0, inv1 = 1.0f / l1;
    const int er = lane >> 2, ec = (lane & 3) * 2;
    const size_t tok0 = (size_t)(b * NSEQ + q0 + wid * 16 + er);
    #pragma unroll
    for (int j = 0; j < 8; j++) {
        const int col = h * HDIM + j * 8 + ec;
        uint32_t hh, ll;
        split_pack(oacc[j][0] * inv0, oacc[j][1] * inv0, hh, ll);
        *(uint32_t*)&Oh[tok0 * INTD + col] = hh;
        *(uint32_t*)&Ol[tok0 * INTD + col] = ll;
        split_pack(oacc[j][2] * inv1, oacc[j][3] * inv1, hh, ll);
        *(uint32_t*)&Oh[(tok0 + 8) * INTD + col] = hh;
        *(uint32_t*)&Ol[(tok0 + 8) * INTD + col] = ll;
    }
}

// ---------------------------------------------------------------------------
// Launch
// ---------------------------------------------------------------------------
extern "C" void kernel_launch(void* const* d_in, const int* in_sizes, int n_in,
                              void* d_out, int out_size)
{
    const float* q  = (const float*)d_in[0];
    const float* k  = (const float*)d_in[1];
    const float* v  = (const float*)d_in[2];
    const float* wq = (const float*)d_in[3];
    const float* bq = (const float*)d_in[4];
    const float* wk = (const float*)d_in[5];
    const float* bk = (const float*)d_in[6];
    const float* wv = (const float*)d_in[7];
    const float* bv = (const float*)d_in[8];
    const float* wo = (const float*)d_in[9];
    const float* bo = (const float*)d_in[10];
    float* out = (float*)d_out;

    __nv_bfloat16 *qh, *ql, *kh, *kl, *vh, *vl;
    __nv_bfloat16 *wqh, *wql, *wkh, *wkl, *wvh, *wvl, *woh, *wol;
    __nv_bfloat16 *Qph, *Qpl, *Kph, *Kpl, *Vph, *Vpl, *Oh, *Ol;
    cudaGetSymbolAddress((void**)&qh, g_qh);   cudaGetSymbolAddress((void**)&ql, g_ql);
    cudaGetSymbolAddress((void**)&kh, g_kh);   cudaGetSymbolAddress((void**)&kl, g_kl);
    cudaGetSymbolAddress((void**)&vh, g_vh);   cudaGetSymbolAddress((void**)&vl, g_vl);
    cudaGetSymbolAddress((void**)&wqh, g_wqh); cudaGetSymbolAddress((void**)&wql, g_wql);
    cudaGetSymbolAddress((void**)&wkh, g_wkh); cudaGetSymbolAddress((void**)&wkl, g_wkl);
    cudaGetSymbolAddress((void**)&wvh, g_wvh); cudaGetSymbolAddress((void**)&wvl, g_wvl);
    cudaGetSymbolAddress((void**)&woh, g_woh); cudaGetSymbolAddress((void**)&wol, g_wol);
    cudaGetSymbolAddress((void**)&Qph, g_Qph); cudaGetSymbolAddress((void**)&Qpl, g_Qpl);
    cudaGetSymbolAddress((void**)&Kph, g_Kph); cudaGetSymbolAddress((void**)&Kpl, g_Kpl);
    cudaGetSymbolAddress((void**)&Vph, g_Vph); cudaGetSymbolAddress((void**)&Vpl, g_Vpl);
    cudaGetSymbolAddress((void**)&Oh, g_Oh);   cudaGetSymbolAddress((void**)&Ol, g_Ol);

    const int nAct = MROWS * EDIM;
    split_kernel<<<nAct / 1024, 256>>>(q, qh, ql, nAct);
    split_kernel<<<nAct / 1024, 256>>>(k, kh, kl, nAct);
    split_kernel<<<nAct / 1024, 256>>>(v, vh, vl, nAct);

    dim3 tblk(32, 8);
    dim3 tgrid(INTD / 32, EDIM / 32);
    transpose_split_kernel<<<tgrid, tblk>>>(wq, wqh, wql, EDIM, INTD);
    transpose_split_kernel<<<tgrid, tblk>>>(wk, wkh, wkl, EDIM, INTD);
    transpose_split_kernel<<<tgrid, tblk>>>(wv, wvh, wvl, EDIM, INTD);
    dim3 tgrid2(EDIM / 32, INTD / 32);
    transpose_split_kernel<<<tgrid2, tblk>>>(wo, woh, wol, INTD, EDIM);

    const int gsmem = 65536 + 1024;
    cudaFuncSetAttribute(gemm_mma, cudaFuncAttributeMaxDynamicSharedMemorySize, gsmem);
    dim3 ggrid(INTD / 128, MROWS / 128);   // (8, 64)
    gemm_mma<<<ggrid, 256, gsmem>>>(qh, ql, wqh, wql, bq, nullptr, Qph, Qpl, EDIM, INTD);
    gemm_mma<<<ggrid, 256, gsmem>>>(kh, kl, wkh, wkl, bk, nullptr, Kph, Kpl, EDIM, INTD);
    gemm_mma<<<ggrid, 256, gsmem>>>(vh, vl, wvh, wvl, bv, nullptr, Vph, Vpl, EDIM, INTD);

    const int asmem = 65536 + 1024;
    cudaFuncSetAttribute(attn_mma, cudaFuncAttributeMaxDynamicSharedMemorySize, asmem);
    dim3 agrid(NSEQ / 128, B_SZ * NHEAD);  // (16, 64)
    attn_mma<<<agrid, 256, asmem>>>(Qph, Qpl, Kph, Kpl, Vph, Vpl, Oh, Ol);

    dim3 ogrid(EDIM / 128, MROWS / 128);
    gemm_mma<<<ogrid, 256, gsmem>>>(Oh, Ol, woh, wol, bo, out, nullptr, nullptr, INTD, EDIM);
}

// round 4
// speedup vs baseline: 4.1127x; 1.2426x over previous
#include <cuda_runtime.h>
#include <cuda_bf16.h>
#include <cstdint>

// Problem constants
#define B_SZ   4
#define NSEQ   2048
#define EDIM   1024
#define INTD   1024
#define NHEAD  16
#define HDIM   64
#define MROWS  (B_SZ * NSEQ)          // 8192
#define KSC    0.1803368801111244f    // (1/sqrt(64)) * log2(e)

// ---------------------------------------------------------------------------
// Device scratch
// ---------------------------------------------------------------------------
__device__ __nv_bfloat16 g_qh[MROWS * EDIM], g_ql[MROWS * EDIM];
__device__ __nv_bfloat16 g_kh[MROWS * EDIM], g_kl[MROWS * EDIM];
__device__ __nv_bfloat16 g_vh[MROWS * EDIM], g_vl[MROWS * EDIM];
__device__ __nv_bfloat16 g_wqh[INTD * EDIM], g_wql[INTD * EDIM];
__device__ __nv_bfloat16 g_wkh[INTD * EDIM], g_wkl[INTD * EDIM];
__device__ __nv_bfloat16 g_wvh[INTD * EDIM], g_wvl[INTD * EDIM];
__device__ __nv_bfloat16 g_woh[EDIM * INTD], g_wol[EDIM * INTD];
__device__ __nv_bfloat16 g_Qph[MROWS * INTD], g_Qpl[MROWS * INTD];
__device__ __nv_bfloat16 g_Kph[MROWS * INTD], g_Kpl[MROWS * INTD];
__device__ __nv_bfloat16 g_Vph[MROWS * INTD], g_Vpl[MROWS * INTD];
__device__ __nv_bfloat16 g_Oh[MROWS * INTD], g_Ol[MROWS * INTD];

// ---------------------------------------------------------------------------
// Helpers
// ---------------------------------------------------------------------------
__device__ __forceinline__ uint32_t smem_u32(const void* p) {
    uint32_t a;
    asm("{ .reg .u64 t; cvta.to.shared.u64 t, %1; cvt.u32.u64 %0, t; }"
        : "=r"(a) : "l"(p));
    return a;
}

__device__ __forceinline__ void cpa16(uint32_t saddr, const void* g) {
    asm volatile("cp.async.cg.shared.global [%0], [%1], 16;"
                 :: "r"(saddr), "l"(g) : "memory");
}
#define CPA_COMMIT() asm volatile("cp.async.commit_group;" ::: "memory")
#define CPA_WAIT(n)  asm volatile("cp.async.wait_group %0;" :: "n"(n) : "memory")

__device__ __forceinline__ void ldsm4(uint32_t* r, uint32_t addr) {
    asm volatile("ldmatrix.sync.aligned.m8n8.x4.shared.b16 {%0,%1,%2,%3}, [%4];"
                 : "=r"(r[0]), "=r"(r[1]), "=r"(r[2]), "=r"(r[3]) : "r"(addr));
}

__device__ __forceinline__ void ldsm4t(uint32_t* r, uint32_t addr) {
    asm volatile("ldmatrix.sync.aligned.m8n8.x4.trans.shared.b16 {%0,%1,%2,%3}, [%4];"
                 : "=r"(r[0]), "=r"(r[1]), "=r"(r[2]), "=r"(r[3]) : "r"(addr));
}

__device__ __forceinline__ void mma_bf16(float* d, const uint32_t* a, const uint32_t* b) {
    asm volatile(
        "mma.sync.aligned.m16n8k16.row.col.f32.bf16.bf16.f32 "
        "{%0,%1,%2,%3}, {%4,%5,%6,%7}, {%8,%9}, {%0,%1,%2,%3};"
        : "+f"(d[0]), "+f"(d[1]), "+f"(d[2]), "+f"(d[3])
        : "r"(a[0]), "r"(a[1]), "r"(a[2]), "r"(a[3]), "r"(b[0]), "r"(b[1]));
}

// MUFU exp2 — separate pipe, overlaps tensor/FMA work
__device__ __forceinline__ float ex2f(float x) {
    float y;
    asm("ex2.approx.f32 %0, %1;" : "=f"(y) : "f"(x));
    return y;
}

// swizzled address in a tile with 128-byte rows (64 bf16) — classic SW128
__device__ __forceinline__ uint32_t swa(uint32_t base, int r, int k) {
    return base + (uint32_t)(r * 128 + ((((k >> 3) ^ (r & 7)) & 7) << 4));
}

// swizzled address in a tile with 64-byte rows (32 bf16); conflict-free for ldsm:
// 16B chunk c' = c ^ ((r>>1)&3)
__device__ __forceinline__ uint32_t swb(uint32_t base, int r, int k) {
    int c = (k >> 3) & 3;
    return base + (uint32_t)(r * 64 + ((c ^ ((r >> 1) & 3)) << 4));
}

__device__ __forceinline__ uint32_t pack_bf16(__nv_bfloat16 x, __nv_bfloat16 y) {
    __nv_bfloat162 t = __halves2bfloat162(x, y);
    return *(uint32_t*)&t;
}

__device__ __forceinline__ void split_pack(float x, float y, uint32_t& hi, uint32_t& lo) {
    __nv_bfloat16 hx = __float2bfloat16_rn(x);
    __nv_bfloat16 hy = __float2bfloat16_rn(y);
    hi = pack_bf16(hx, hy);
    lo = pack_bf16(__float2bfloat16_rn(x - __bfloat162float(hx)),
                   __float2bfloat16_rn(y - __bfloat162float(hy)));
}

// ---------------------------------------------------------------------------
// Split fp32 -> bf16 hi/lo
// ---------------------------------------------------------------------------
__global__ __launch_bounds__(256) void split_kernel(
    const float* __restrict__ x, __nv_bfloat16* __restrict__ h,
    __nv_bfloat16* __restrict__ l, int n)
{
    int i = (blockIdx.x * 256 + threadIdx.x) * 4;
    if (i >= n) return;
    float4 v = *(const float4*)&x[i];
    uint32_t h0, l0, h1, l1;
    split_pack(v.x, v.y, h0, l0);
    split_pack(v.z, v.w, h1, l1);
    *(uint2*)&h[i] = make_uint2(h0, h1);
    *(uint2*)&l[i] = make_uint2(l0, l1);
}

__global__ __launch_bounds__(256) void transpose_split_kernel(
    const float* __restrict__ W, __nv_bfloat16* __restrict__ Th,
    __nv_bfloat16* __restrict__ Tl, int K, int N)
{
    __shared__ float t[32][33];
    int n0 = blockIdx.x * 32, k0 = blockIdx.y * 32;
    int tx = threadIdx.x, ty = threadIdx.y;   // 32 x 8
    #pragma unroll
    for (int i = 0; i < 32; i += 8)
        t[ty + i][tx] = W[(size_t)(k0 + ty + i) * N + n0 + tx];
    __syncthreads();
    #pragma unroll
    for (int i = 0; i < 32; i += 8) {
        float v = t[tx][ty + i];
        __nv_bfloat16 hh = __float2bfloat16_rn(v);
        size_t o = (size_t)(n0 + ty + i) * K + k0 + tx;
        Th[o] = hh;
        Tl[o] = __float2bfloat16_rn(v - __bfloat162float(hh));
    }
}

// ---------------------------------------------------------------------------
// Pipelined split-bf16 GEMM: C[M,N] = A[M,K] @ B[N,K]^T + bias
// BM=128, BN=128, BK=32; 3-stage cp.async pipeline; 8 warps (2m x 4n).
// grid.z selects (A,B,bias,C) set for fused QKV; out-proj uses set 0 w/ Cf.
// ---------------------------------------------------------------------------
struct GemmSet {
    const __nv_bfloat16 *Ah, *Al, *Bh, *Bl;
    const float* bias;
    float* Cf;
    __nv_bfloat16 *Ch, *Cl;
};

__global__ __launch_bounds__(256) void gemm_mma(
    GemmSet s0, GemmSet s1, GemmSet s2, int K, int N)
{
    extern __shared__ char smraw[];
    const uint32_t base = (smem_u32(smraw) + 1023u) & ~1023u;

    const GemmSet& S = (blockIdx.z == 0) ? s0 : (blockIdx.z == 1) ? s1 : s2;
    const __nv_bfloat16* __restrict__ Ah = S.Ah;
    const __nv_bfloat16* __restrict__ Al = S.Al;
    const __nv_bfloat16* __restrict__ Bh = S.Bh;
    const __nv_bfloat16* __restrict__ Bl = S.Bl;

    const int tid = threadIdx.x, lane = tid & 31, wid = tid >> 5;
    const int wm = wid >> 2, wn = wid & 3;
    const int bm = blockIdx.y * 128, bn = blockIdx.x * 128;
    const int lr = lane & 15, lco = (lane >> 4) * 8;
    const int NCH = K / 32;

    // per-thread load slots: 4 arrays x 128 rows x 4 chunks(16B) = 2048; 8/thread
    int l_which[8], l_r[8], l_c[8];
    uint32_t l_sa[8];
    #pragma unroll
    for (int t = 0; t < 8; t++) {
        int id = tid + t * 256;
        l_which[t] = id >> 9;
        int rem = id & 511;
        l_r[t] = rem >> 2;
        l_c[t] = rem & 3;
        l_sa[t] = (uint32_t)(l_which[t] * 8192 + l_r[t] * 64 +
                             ((l_c[t] ^ ((l_r[t] >> 1) & 3)) << 4));
    }

    auto load_stage = [&](int chunk, int stage) {
        const int k0 = chunk * 32;
        const uint32_t sb = base + stage * 32768;
        #pragma unroll
        for (int t = 0; t < 8; t++) {
            const __nv_bfloat16* src = (l_which[t] == 0) ? Ah : (l_which[t] == 1) ? Al
                                     : (l_which[t] == 2) ? Bh : Bl;
            const int row = ((l_which[t] < 2) ? bm : bn) + l_r[t];
            cpa16(sb + l_sa[t], &src[(size_t)row * K + k0 + l_c[t] * 8]);
        }
        CPA_COMMIT();
    };

    load_stage(0, 0);
    load_stage(1, 1);
    load_stage(2, 2);

    float acc[4][4][4] = {};

    for (int i = 0; i < NCH; i++) {
        CPA_WAIT(2);
        __syncthreads();
        const uint32_t st = base + (i % 3) * 32768;
        const uint32_t As_h = st, As_l = st + 8192, Bs_h = st + 16384, Bs_l = st + 24576;

        #pragma unroll
        for (int ks = 0; ks < 2; ks++) {
            const int kk = ks * 16 + lco;
            uint32_t ah[4][4], al_[4][4], bhf[4][2], blf[4][2];
            #pragma unroll
            for (int m = 0; m < 4; m++) {
                const int r = wm * 64 + m * 16 + lr;
                ldsm4(ah[m], swb(As_h, r, kk));
                ldsm4(al_[m], swb(As_l, r, kk));
            }
            #pragma unroll
            for (int bb = 0; bb < 2; bb++) {
                const int r = wn * 32 + bb * 16 + lr;
                uint32_t t4[4];
                ldsm4(t4, swb(Bs_h, r, kk));
                bhf[2*bb][0] = t4[0]; bhf[2*bb][1] = t4[2];
                bhf[2*bb+1][0] = t4[1]; bhf[2*bb+1][1] = t4[3];
                ldsm4(t4, swb(Bs_l, r, kk));
                blf[2*bb][0] = t4[0]; blf[2*bb][1] = t4[2];
                blf[2*bb+1][0] = t4[1]; blf[2*bb+1][1] = t4[3];
            }
            #pragma unroll
            for (int m = 0; m < 4; m++)
                #pragma unroll
                for (int j = 0; j < 4; j++) {
                    mma_bf16(acc[m][j], ah[m],  bhf[j]);
                    mma_bf16(acc[m][j], ah[m],  blf[j]);
                    mma_bf16(acc[m][j], al_[m], bhf[j]);
                }
        }
        __syncthreads();
        if (i + 3 < NCH) load_stage(i + 3, i % 3);
        else CPA_COMMIT();
    }

    const int er = lane >> 2, ec = (lane & 3) * 2;
    #pragma unroll
    for (int m = 0; m < 4; m++) {
        const int r0 = bm + wm * 64 + m * 16 + er;
        #pragma unroll
        for (int j = 0; j < 4; j++) {
            const int col = bn + wn * 32 + j * 8 + ec;
            const float b0 = S.bias[col], b1 = S.bias[col + 1];
            const float v00 = acc[m][j][0] + b0, v01 = acc[m][j][1] + b1;
            const float v10 = acc[m][j][2] + b0, v11 = acc[m][j][3] + b1;
            if (S.Cf) {
                *(float2*)&S.Cf[(size_t)r0 * N + col]       = make_float2(v00, v01);
                *(float2*)&S.Cf[(size_t)(r0 + 8) * N + col] = make_float2(v10, v11);
            } else {
                uint32_t h, l;
                split_pack(v00, v01, h, l);
                *(uint32_t*)&S.Ch[(size_t)r0 * N + col] = h;
                *(uint32_t*)&S.Cl[(size_t)r0 * N + col] = l;
                split_pack(v10, v11, h, l);
                *(uint32_t*)&S.Ch[(size_t)(r0 + 8) * N + col] = h;
                *(uint32_t*)&S.Cl[(size_t)(r0 + 8) * N + col] = l;
            }
        }
    }
}

// ---------------------------------------------------------------------------
// Flash attention, cp.async 2-stage KV pipeline, MUFU softmax.
// CTA: one (b,h), 128 q-rows; 8 warps (16 q each); KV tiles of 64 keys.
// ---------------------------------------------------------------------------
__global__ __launch_bounds__(256) void attn_mma(
    const __nv_bfloat16* __restrict__ Qh, const __nv_bfloat16* __restrict__ Ql,
    const __nv_bfloat16* __restrict__ Kh, const __nv_bfloat16* __restrict__ Kl,
    const __nv_bfloat16* __restrict__ Vh, const __nv_bfloat16* __restrict__ Vl,
    __nv_bfloat16* __restrict__ Oh, __nv_bfloat16* __restrict__ Ol)
{
    extern __shared__ char smraw[];
    const uint32_t base = (smem_u32(smraw) + 1023u) & ~1023u;
    const uint32_t Qs_h = base, Qs_l = base + 16384;
    const uint32_t KV0 = base + 32768;    // per stage: Kh,Kl,Vh,Vl 8KB each

    const int tid = threadIdx.x, lane = tid & 31, wid = tid >> 5;
    const int b = blockIdx.y >> 4, h = blockIdx.y & 15;
    const int q0 = blockIdx.x * 128;
    const int lr = lane & 15, lco = (lane >> 4) * 8;
    const size_t tokb = (size_t)(b * NSEQ);

    // KV load slots: 4 arrays x 64 rows x 8 chunks = 2048; 8/thread
    int kv_which[8], kv_r[8], kv_j[8];
    uint32_t kv_sa[8];
    #pragma unroll
    for (int t = 0; t < 8; t++) {
        int id = tid + t * 256;
        kv_which[t] = id >> 9;
        int rem = id & 511;
        kv_r[t] = rem >> 3;
        kv_j[t] = rem & 7;
        kv_sa[t] = (uint32_t)(kv_which[t] * 8192 + kv_r[t] * 128 +
                              ((kv_j[t] ^ (kv_r[t] & 7)) << 4));
    }

    auto load_kv = [&](int kt, int stage) {
        const size_t tok0 = tokb + kt * 64;
        const uint32_t sb = KV0 + stage * 32768;
        #pragma unroll
        for (int t = 0; t < 8; t++) {
            const __nv_bfloat16* src = (kv_which[t] == 0) ? Kh : (kv_which[t] == 1) ? Kl
                                     : (kv_which[t] == 2) ? Vh : Vl;
            cpa16(sb + kv_sa[t], &src[(tok0 + kv_r[t]) * INTD + h * HDIM + kv_j[t] * 8]);
        }
        CPA_COMMIT();
    };

    // Q load (group 0, together with KV tile 0)
    #pragma unroll
    for (int t = 0; t < 8; t++) {
        int id = tid + t * 256;           // 0..2047: 2 arrays x 128 rows x 8 chunks
        int which = id >> 10;
        int rem = id & 1023;
        int r = rem >> 3, j = rem & 7;
        const __nv_bfloat16* src = which ? Ql : Qh;
        cpa16((which ? Qs_l : Qs_h) + r * 128 + ((j ^ (r & 7)) << 4),
              &src[(tokb + q0 + r) * INTD + h * HDIM + j * 8]);
    }
    load_kv(0, 0);    // commits group (Q + KV0)
    load_kv(1, 1);

    float oacc[8][4] = {};
    float m0 = -1e30f, m1 = -1e30f, l0 = 0.f, l1 = 0.f;

    for (int kt = 0; kt < NSEQ / 64; kt++) {
        CPA_WAIT(1);
        __syncthreads();
        const uint32_t st = KV0 + (kt & 1) * 32768;
        const uint32_t Ks_h = st, Ks_l = st + 8192, Vs_h = st + 16384, Vs_l = st + 24576;

        // ---- S = (Qh+Ql)(Kh+Kl)^T (3 combos) ----
        float sacc[8][4] = {};
        #pragma unroll
        for (int ks = 0; ks < 4; ks++) {
            const int kk = ks * 16 + lco;
            uint32_t qf_h[4], qf_l[4];
            ldsm4(qf_h, swa(Qs_h, wid * 16 + lr, kk));
            ldsm4(qf_l, swa(Qs_l, wid * 16 + lr, kk));
            uint32_t kb_h[8][2], kb_l[8][2];
            #pragma unroll
            for (int bb = 0; bb < 4; bb++) {
                uint32_t t4[4];
                ldsm4(t4, swa(Ks_h, bb * 16 + lr, kk));
                kb_h[2*bb][0] = t4[0]; kb_h[2*bb][1] = t4[2];
                kb_h[2*bb+1][0] = t4[1]; kb_h[2*bb+1][1] = t4[3];
                ldsm4(t4, swa(Ks_l, bb * 16 + lr, kk));
                kb_l[2*bb][0] = t4[0]; kb_l[2*bb][1] = t4[2];
                kb_l[2*bb+1][0] = t4[1]; kb_l[2*bb+1][1] = t4[3];
            }
            #pragma unroll
            for (int j = 0; j < 8; j++) {
                mma_bf16(sacc[j], qf_h, kb_h[j]);
                mma_bf16(sacc[j], qf_h, kb_l[j]);
                mma_bf16(sacc[j], qf_l, kb_h[j]);
            }
        }

        // ---- online softmax (MUFU exp2, scale folded) ----
        float mx0 = -1e30f, mx1 = -1e30f;
        #pragma unroll
        for (int j = 0; j < 8; j++) {
            mx0 = fmaxf(mx0, fmaxf(sacc[j][0], sacc[j][1]));
            mx1 = fmaxf(mx1, fmaxf(sacc[j][2], sacc[j][3]));
        }
        mx0 = fmaxf(mx0, __shfl_xor_sync(0xffffffffu, mx0, 1));
        mx0 = fmaxf(mx0, __shfl_xor_sync(0xffffffffu, mx0, 2));
        mx1 = fmaxf(mx1, __shfl_xor_sync(0xffffffffu, mx1, 1));
        mx1 = fmaxf(mx1, __shfl_xor_sync(0xffffffffu, mx1, 2));
        const float mn0 = fmaxf(m0, mx0), mn1 = fmaxf(m1, mx1);
        const float c0 = ex2f((m0 - mn0) * KSC), c1 = ex2f((m1 - mn1) * KSC);
        m0 = mn0; m1 = mn1;
        const float mb0 = mn0 * KSC, mb1 = mn1 * KSC;

        float s0 = 0.f, s1 = 0.f;
        uint32_t pah0[8], pah1[8], pal0[8], pal1[8];
        #pragma unroll
        for (int j = 0; j < 8; j++) {
            const float p00 = ex2f(fmaf(sacc[j][0], KSC, -mb0));
            const float p01 = ex2f(fmaf(sacc[j][1], KSC, -mb0));
            const float p10 = ex2f(fmaf(sacc[j][2], KSC, -mb1));
            const float p11 = ex2f(fmaf(sacc[j][3], KSC, -mb1));
            s0 += p00 + p01; s1 += p10 + p11;
            split_pack(p00, p01, pah0[j], pal0[j]);
            split_pack(p10, p11, pah1[j], pal1[j]);
        }
        s0 += __shfl_xor_sync(0xffffffffu, s0, 1);
        s0 += __shfl_xor_sync(0xffffffffu, s0, 2);
        s1 += __shfl_xor_sync(0xffffffffu, s1, 1);
        s1 += __shfl_xor_sync(0xffffffffu, s1, 2);
        l0 = l0 * c0 + s0; l1 = l1 * c1 + s1;
        #pragma unroll
        for (int j = 0; j < 8; j++) {
            oacc[j][0] *= c0; oacc[j][1] *= c0;
            oacc[j][2] *= c1; oacc[j][3] *= c1;
        }

        // ---- O += P @ V (3 combos) ----
        #pragma unroll
        for (int t = 0; t < 4; t++) {
            const uint32_t a_h[4] = {pah0[2*t], pah1[2*t], pah0[2*t+1], pah1[2*t+1]};
            const uint32_t a_l[4] = {pal0[2*t], pal1[2*t], pal0[2*t+1], pal1[2*t+1]};
            uint32_t vb_h[8][2], vb_l[8][2];
            #pragma unroll
            for (int c = 0; c < 4; c++) {
                uint32_t t4[4];
                ldsm4t(t4, swa(Vs_h, t * 16 + lr, c * 16 + lco));
                vb_h[2*c][0] = t4[0]; vb_h[2*c][1] = t4[1];
                vb_h[2*c+1][0] = t4[2]; vb_h[2*c+1][1] = t4[3];
                ldsm4t(t4, swa(Vs_l, t * 16 + lr, c * 16 + lco));
                vb_l[2*c][0] = t4[0]; vb_l[2*c][1] = t4[1];
                vb_l[2*c+1][0] = t4[2]; vb_l[2*c+1][1] = t4[3];
            }
            #pragma unroll
            for (int j = 0; j < 8; j++) {
                mma_bf16(oacc[j], a_h, vb_h[j]);
                mma_bf16(oacc[j], a_h, vb_l[j]);
                mma_bf16(oacc[j], a_l, vb_h[j]);
            }
        }
        __syncthreads();
        if (kt + 2 < NSEQ / 64) load_kv(kt + 2, kt & 1);
        else CPA_COMMIT();
    }

    // epilogue
    const float inv0 = 1.0f / l0, inv1 = 1.0f / l1;
    const int er = lane >> 2, ec = (lane & 3) * 2;
    const size_t tok0 = tokb + q0 + wid * 16 + er;
    #pragma unroll
    for (int j = 0; j < 8; j++) {
        const int col = h * HDIM + j * 8 + ec;
        uint32_t hh, ll;
        split_pack(oacc[j][0] * inv0, oacc[j][1] * inv0, hh, ll);
        *(uint32_t*)&Oh[tok0 * INTD + col] = hh;
        *(uint32_t*)&Ol[tok0 * INTD + col] = ll;
        split_pack(oacc[j][2] * inv1, oacc[j][3] * inv1, hh, ll);
        *(uint32_t*)&Oh[(tok0 + 8) * INTD + col] = hh;
        *(uint32_t*)&Ol[(tok0 + 8) * INTD + col] = ll;
    }
}

// ---------------------------------------------------------------------------
// Launch
// ---------------------------------------------------------------------------
extern "C" void kernel_launch(void* const* d_in, const int* in_sizes, int n_in,
                              void* d_out, int out_size)
{
    const float* q  = (const float*)d_in[0];
    const float* k  = (const float*)d_in[1];
    const float* v  = (const float*)d_in[2];
    const float* wq = (const float*)d_in[3];
    const float* bq = (const float*)d_in[4];
    const float* wk = (const float*)d_in[5];
    const float* bk = (const float*)d_in[6];
    const float* wv = (const float*)d_in[7];
    const float* bv = (const float*)d_in[8];
    const float* wo = (const float*)d_in[9];
    const float* bo = (const float*)d_in[10];
    float* out = (float*)d_out;

    __nv_bfloat16 *qh, *ql, *kh, *kl, *vh, *vl;
    __nv_bfloat16 *wqh, *wql, *wkh, *wkl, *wvh, *wvl, *woh, *wol;
    __nv_bfloat16 *Qph, *Qpl, *Kph, *Kpl, *Vph, *Vpl, *Oh, *Ol;
    cudaGetSymbolAddress((void**)&qh, g_qh);   cudaGetSymbolAddress((void**)&ql, g_ql);
    cudaGetSymbolAddress((void**)&kh, g_kh);   cudaGetSymbolAddress((void**)&kl, g_kl);
    cudaGetSymbolAddress((void**)&vh, g_vh);   cudaGetSymbolAddress((void**)&vl, g_vl);
    cudaGetSymbolAddress((void**)&wqh, g_wqh); cudaGetSymbolAddress((void**)&wql, g_wql);
    cudaGetSymbolAddress((void**)&wkh, g_wkh); cudaGetSymbolAddress((void**)&wkl, g_wkl);
    cudaGetSymbolAddress((void**)&wvh, g_wvh); cudaGetSymbolAddress((void**)&wvl, g_wvl);
    cudaGetSymbolAddress((void**)&woh, g_woh); cudaGetSymbolAddress((void**)&wol, g_wol);
    cudaGetSymbolAddress((void**)&Qph, g_Qph); cudaGetSymbolAddress((void**)&Qpl, g_Qpl);
    cudaGetSymbolAddress((void**)&Kph, g_Kph); cudaGetSymbolAddress((void**)&Kpl, g_Kpl);
    cudaGetSymbolAddress((void**)&Vph, g_Vph); cudaGetSymbolAddress((void**)&Vpl, g_Vpl);
    cudaGetSymbolAddress((void**)&Oh, g_Oh);   cudaGetSymbolAddress((void**)&Ol, g_Ol);

    const int nAct = MROWS * EDIM;
    split_kernel<<<nAct / 1024, 256>>>(q, qh, ql, nAct);
    split_kernel<<<nAct / 1024, 256>>>(k, kh, kl, nAct);
    split_kernel<<<nAct / 1024, 256>>>(v, vh, vl, nAct);

    dim3 tblk(32, 8);
    dim3 tgrid(INTD / 32, EDIM / 32);
    transpose_split_kernel<<<tgrid, tblk>>>(wq, wqh, wql, EDIM, INTD);
    transpose_split_kernel<<<tgrid, tblk>>>(wk, wkh, wkl, EDIM, INTD);
    transpose_split_kernel<<<tgrid, tblk>>>(wv, wvh, wvl, EDIM, INTD);
    dim3 tgrid2(EDIM / 32, INTD / 32);
    transpose_split_kernel<<<tgrid2, tblk>>>(wo, woh, wol, INTD, EDIM);

    const int gsmem = 3 * 32768 + 1024;
    cudaFuncSetAttribute(gemm_mma, cudaFuncAttributeMaxDynamicSharedMemorySize, gsmem);

    GemmSet sq{qh, ql, wqh, wql, bq, nullptr, Qph, Qpl};
    GemmSet sk{kh, kl, wkh, wkl, bk, nullptr, Kph, Kpl};
    GemmSet sv{vh, vl, wvh, wvl, bv, nullptr, Vph, Vpl};
    dim3 ggrid(INTD / 128, MROWS / 128, 3);   // fused QKV
    gemm_mma<<<ggrid, 256, gsmem>>>(sq, sk, sv, EDIM, INTD);

    const int asmem = 32768 + 2 * 32768 + 1024;
    cudaFuncSetAttribute(attn_mma, cudaFuncAttributeMaxDynamicSharedMemorySize, asmem);
    dim3 agrid(NSEQ / 128, B_SZ * NHEAD);  // (16, 64)
    attn_mma<<<agrid, 256, asmem>>>(Qph, Qpl, Kph, Kpl, Vph, Vpl, Oh, Ol);

    GemmSet so{Oh, Ol, woh, wol, bo, out, nullptr, nullptr};
    dim3 ogrid(EDIM / 128, MROWS / 128, 1);
    gemm_mma<<<ogrid, 256, gsmem>>>(so, so, so, INTD, EDIM);
}